// round 3
// baseline (speedup 1.0000x reference)
#include <cuda_runtime.h>

#define NB 4
#define NT 1024
#define NL 64
#define NC 256
#define HALF 256
#define VD 512

// u[b, l, d] accumulator scratch: 4*64*256 floats = 256 KB
__device__ float g_u[NB * NL * HALF];

// Zero scratch + output (d_out is poisoned to 0xAA by the harness).
__global__ void k0_zero(float* __restrict__ out) {
    int i = blockIdx.x * 256 + threadIdx.x;   // grid 256x256 = 65536 == NB*NL*HALF
    g_u[i] = 0.0f;
    if (i < NB * NC) out[i] = 0.0f;
}

// Phase 1: u[b, label[b,t], d] += scores[b,t] * weight[indices[b,t], off + d]
// One warp per token; each lane handles 8 d's via two float4 loads.
__global__ void k1_gather(const int* __restrict__ indices,
                          const float* __restrict__ scores,
                          const int* __restrict__ label,
                          const int* __restrict__ idxp,
                          const float* __restrict__ weight) {
    int tok  = (blockIdx.x * blockDim.x + threadIdx.x) >> 5;
    int lane = threadIdx.x & 31;
    int off  = (idxp[0] == 1) ? HALF : 0;
    int idx  = indices[tok];
    float s  = scores[tok];
    int lab  = label[tok];
    int b    = tok >> 10;                      // T = 1024
    const float4* row = reinterpret_cast<const float4*>(weight + (size_t)idx * VD + off);
    float* dst = g_u + ((b * NL + lab) << 8);  // * HALF
    float4 v0 = __ldg(row + lane);             // d = lane*4 .. lane*4+3
    float4 v1 = __ldg(row + lane + 32);        // d = 128 + lane*4 ..
    int d0 = lane * 4;
    atomicAdd(dst + d0 + 0,       v0.x * s);
    atomicAdd(dst + d0 + 1,       v0.y * s);
    atomicAdd(dst + d0 + 2,       v0.z * s);
    atomicAdd(dst + d0 + 3,       v0.w * s);
    atomicAdd(dst + 128 + d0 + 0, v1.x * s);
    atomicAdd(dst + 128 + d0 + 1, v1.y * s);
    atomicAdd(dst + 128 + d0 + 2, v1.z * s);
    atomicAdd(dst + 128 + d0 + 3, v1.w * s);
}

// Phase 2: out[b,c] += sum_{d in chunk} u[b,l,d] * W[l, off+d, c]
// grid (l = 64, dchunk = 4), 256 threads, thread owns column c.
__global__ void k2_gemm(const float* __restrict__ W,
                        const int* __restrict__ idxp,
                        float* __restrict__ out) {
    __shared__ float su[64 * 4];               // su[dd*4 + b]
    int l   = blockIdx.x;
    int d0  = blockIdx.y * 64;
    int tid = threadIdx.x;
    int off = (idxp[0] == 1) ? HALF : 0;
    {
        int b  = tid >> 6;
        int dd = tid & 63;
        su[dd * 4 + b] = g_u[((b * NL + l) << 8) + d0 + dd];
    }
    __syncthreads();

    const float* wp = W + ((size_t)l * VD + off + d0) * NC + tid;
    float a0 = 0.f, a1 = 0.f, a2 = 0.f, a3 = 0.f;
#pragma unroll 16
    for (int dd = 0; dd < 64; dd++) {
        float w  = __ldg(wp);
        wp += NC;
        float u0 = su[dd * 4 + 0];
        float u1 = su[dd * 4 + 1];
        float u2 = su[dd * 4 + 2];
        float u3 = su[dd * 4 + 3];
        a0 += u0 * w;
        a1 += u1 * w;
        a2 += u2 * w;
        a3 += u3 * w;
    }
    atomicAdd(out + 0 * NC + tid, a0);
    atomicAdd(out + 1 * NC + tid, a1);
    atomicAdd(out + 2 * NC + tid, a2);
    atomicAdd(out + 3 * NC + tid, a3);
}

extern "C" void kernel_launch(void* const* d_in, const int* in_sizes, int n_in,
                              void* d_out, int out_size) {
    const int*   indices = (const int*)  d_in[0];
    const float* scores  = (const float*)d_in[1];
    const float* W       = (const float*)d_in[2];
    const int*   label   = (const int*)  d_in[3];
    const int*   index   = (const int*)  d_in[4];
    const float* weight  = (const float*)d_in[5];
    float* out = (float*)d_out;

    k0_zero<<<256, 256>>>(out);
    k1_gather<<<512, 256>>>(indices, scores, label, index, weight);
    dim3 g2(64, 4);
    k2_gemm<<<g2, 256>>>(W, index, out);
}